// round 15
// baseline (speedup 1.0000x reference)
#include <cuda_runtime.h>
#include <cstdint>

#define B_  4
#define C_  64
#define H_  96
#define W_  96
#define O_  128
#define HW_ (H_*W_)
#define K2_ 9
#define NJ_ 27
#define CK_ (C_*K2_)   // 576
#define CG_ 4
#define CPG (C_/CG_)   // 16

// scratch
__device__ float g_part[(size_t)CG_*B_*NJ_*HW_];
__device__ float g_Wt[(size_t)CK_*O_];   // transposed weights, k2-major: [(k2*64+c)][o]

__device__ __forceinline__ void cp4z(float* s, const float* g, unsigned ssz) {
    unsigned sa = (unsigned)__cvta_generic_to_shared(s);
    asm volatile("cp.async.ca.shared.global [%0], [%1], 4, %2;"
                 :: "r"(sa), "l"(g), "r"(ssz));
}
__device__ __forceinline__ void cp16(float* s, const float* g) {
    unsigned sa = (unsigned)__cvta_generic_to_shared(s);
    asm volatile("cp.async.cg.shared.global [%0], [%1], 16;"
                 :: "r"(sa), "l"(g));
}
__device__ __forceinline__ unsigned long long pack2(float v) {
    unsigned long long r;
    unsigned int u = __float_as_uint(v);
    asm("mov.b64 %0, {%1, %1};" : "=l"(r) : "r"(u));
    return r;
}

// ---------------------------------------------------------------------------
// Kernel A: offset+modulator 3x3 conv (unchanged from R13/R14)
// ---------------------------------------------------------------------------
__global__ void __launch_bounds__(256) conv_offmod_partial(
    const float* __restrict__ x, const float* __restrict__ ow,
    const float* __restrict__ mw)
{
    __shared__ float ws[CPG*14*9];
    __shared__ float xs[2][34*36];

    const int tx = threadIdx.x;
    const int ty = threadIdx.y;
    const int tid = ty*8 + tx;
    const int zz = blockIdx.z;
    const int half = zz & 1;
    const int g = (zz >> 1) & 3;
    const int b = zz >> 3;
    const int JB = half * 14;
    const int jn = half ? 13 : 14;
    const int c0 = g * CPG;
    const int x0t = blockIdx.x*32 - 1;
    const int y0t = blockIdx.y*32 - 1;

    const int jn9 = jn * 9;
    for (int idx = tid; idx < CPG*jn9; idx += 256) {
        int c = idx / jn9, r = idx % jn9;
        int j = r / 9 + JB, t = r % 9;
        float v = (j < 18) ? ow[(j*64 + c0 + c)*9 + t]
                           : mw[((j-18)*64 + c0 + c)*9 + t];
        ws[idx] = v;
    }

    float acc[14][4];
#pragma unroll
    for (int j = 0; j < 14; j++)
#pragma unroll
        for (int i = 0; i < 4; i++) acc[j][i] = 0.f;

    const float* xb = x + (b*C_ + c0)*HW_;

    auto issueX = [&](int buf, int c) {
        const float* xc = xb + c*HW_;
#pragma unroll
        for (int it = 0; it < 5; it++) {
            int idx = tid + it*256;
            if (idx < 34*34) {
                int r = idx / 34, cc = idx % 34;
                int gy = y0t + r, gx = x0t + cc;
                bool ok = (gy >= 0 && gy < H_ && gx >= 0 && gx < W_);
                const float* gp = xc + (ok ? gy*W_ + gx : 0);
                cp4z(&xs[buf][r*36 + cc], gp, ok ? 4u : 0u);
            }
        }
        asm volatile("cp.async.commit_group;");
    };

    issueX(0, 0);

    for (int c = 0; c < CPG; c++) {
        if (c + 1 < CPG) {
            issueX((c+1) & 1, c+1);
            asm volatile("cp.async.wait_group 1;");
        } else {
            asm volatile("cp.async.wait_group 0;");
        }
        __syncthreads();

        const float* xt = xs[c & 1];
        float xv[3][6];
#pragma unroll
        for (int dy = 0; dy < 3; dy++)
#pragma unroll
            for (int dx = 0; dx < 6; dx++)
                xv[dy][dx] = xt[(ty + dy)*36 + tx*4 + dx];

        const float* wc = ws + c*jn9;
#pragma unroll
        for (int j = 0; j < 14; j++) {
            if (j < jn) {
#pragma unroll
                for (int t = 0; t < 9; t++) {
                    float wv = wc[j*9 + t];
#pragma unroll
                    for (int i = 0; i < 4; i++)
                        acc[j][i] = fmaf(wv, xv[t/3][t%3 + i], acc[j][i]);
                }
            }
        }
        __syncthreads();
    }

    const int h  = y0t + 1 + ty;
    const int w0 = x0t + 1 + tx*4;
    float* outb = g_part + ((size_t)(g*B_ + b)*NJ_ + JB)*HW_ + h*W_ + w0;
#pragma unroll
    for (int j = 0; j < 14; j++) {
        if (j < jn) {
            float4 v = make_float4(acc[j][0], acc[j][1], acc[j][2], acc[j][3]);
            *(float4*)(outb + (size_t)j*HW_) = v;
        }
    }
}

// ---------------------------------------------------------------------------
// Kernel T: transpose weights, k2-major: g_Wt[(k2*64+c)*O + o] = dw[o][c*9+k2]
// ---------------------------------------------------------------------------
__global__ void transpose_w(const float* __restrict__ dw)
{
    int i = blockIdx.x*256 + threadIdx.x;
    if (i < O_*CK_) {
        int o = i / CK_, r = i % CK_;
        int c = r / 9, k2 = r % 9;
        g_Wt[(size_t)(k2*C_ + c)*O_ + o] = dw[i];
    }
}

// ---------------------------------------------------------------------------
// Kernel F: FUSED gather + GEMM, k2-major, single sync per chunk.
// V: 3-stage buffer; W: 2-stage cp.async.
// Params packed: wgt float4 + gof ushort4 {cy0*W, cy1*W, cx0, cx1}.
// ---------------------------------------------------------------------------
#define KCM 32
#define NPAR (K2_*128)          // 1152
#define WSF (KCM*128)           // 4096 floats per W buffer
#define VSF (KCM*128)           // 4096 floats per V buffer
#define CSWZ(cx) ((cx) ^ (((cx) >> 3) & 1))

__global__ void __launch_bounds__(256, 2) fused_kernel(
    const float* __restrict__ x, const float* __restrict__ ob,
    const float* __restrict__ mb, float* __restrict__ out)
{
    extern __shared__ float sm[];
    float4*  wgt4 = (float4*)sm;                    // [1152] float4 (18432 B)
    ushort4* gof2 = (ushort4*)(sm + 4*NPAR);        // [1152] ushort4 (9216 B)
    float*   wsb  = sm + 4*NPAR + 2*NPAR;           // 2 x 4096 floats (32768 B)
    float*   vsb  = wsb + 2*WSF;                    // 3 x 4096 floats (49152 B)

    const int tid = threadIdx.x;
    const int b   = blockIdx.y;
    const int px0 = blockIdx.x * 128;

    const float* xb = x + b*C_*HW_;

    // ---- stage 0: bilinear params ----
    for (int t = tid; t < NPAR; t += 256) {
        int k2 = t >> 7, p = t & 127;
        int pg = px0 + p;
        int h  = pg / W_, w = pg % W_;

        float dy = ob[2*k2], dx = ob[2*k2+1], mv = mb[k2];
#pragma unroll
        for (int g = 0; g < CG_; g++) {
            const float* pb = g_part + (((size_t)g*B_ + b)*NJ_)*HW_ + pg;
            dy += pb[(size_t)(2*k2)*HW_];
            dx += pb[(size_t)(2*k2+1)*HW_];
            mv += pb[(size_t)(18+k2)*HW_];
        }
        float m = 2.f / (1.f + __expf(-mv));

        float py = (float)(h - 1 + k2/3) + dy;
        float px = (float)(w - 1 + k2%3) + dx;
        float fy = floorf(py), fx = floorf(px);
        float ly = py - fy,    lx = px - fx;
        int y0 = (int)fy, x0i = (int)fx;
        float vy0 = (y0   >= 0 && y0   < H_) ? 1.f : 0.f;
        float vy1 = (y0+1 >= 0 && y0+1 < H_) ? 1.f : 0.f;
        float vx0 = (x0i   >= 0 && x0i   < W_) ? 1.f : 0.f;
        float vx1 = (x0i+1 >= 0 && x0i+1 < W_) ? 1.f : 0.f;
        int cy0 = min(max(y0, 0), H_-1),   cy1 = min(max(y0+1, 0), H_-1);
        int cx0 = min(max(x0i, 0), W_-1),  cx1 = min(max(x0i+1, 0), W_-1);
        wgt4[t] = make_float4((1.f-ly)*(1.f-lx)*vy0*vx0*m,
                              (1.f-ly)*lx      *vy0*vx1*m,
                              ly*(1.f-lx)      *vy1*vx0*m,
                              ly*lx            *vy1*vx1*m);
        gof2[t] = make_ushort4((unsigned short)(cy0*W_),
                               (unsigned short)(cy1*W_),
                               (unsigned short)cx0,
                               (unsigned short)cx1);
    }
    __syncthreads();

    const int lane = tid & 31;
    const int wrow = tid >> 5;   // 0..7

    // gather one 32-k chunk (single k2) into vbuf
    auto do_gather = [&](int kc, float* vbuf) {
        const int k2    = kc >> 6;
        const int cbase = kc & 63;
        const float* xcb = xb + (size_t)cbase*HW_;
#pragma unroll
        for (int rep = 0; rep < 4; rep++) {
            int p = lane + rep*32;
            int t = k2*128 + p;
            float4  wv = wgt4[t];
            ushort4 gg = gof2[t];
            const float* r0 = xcb + gg.x;
            const float* r1 = xcb + gg.y;
            const float* q0 = r0 + gg.z;
            const float* q1 = r0 + gg.w;
            const float* q2 = r1 + gg.z;
            const float* q3 = r1 + gg.w;
            int chunk = p >> 2;
            float* vdst = vbuf + (CSWZ(chunk) << 2) + (p & 3);
#pragma unroll
            for (int it = 0; it < 4; it++) {
                int kk = wrow + it*8;
                size_t coff = (size_t)kk*HW_;
                float v = wv.x*__ldg(q0 + coff) + wv.y*__ldg(q1 + coff)
                        + wv.z*__ldg(q2 + coff) + wv.w*__ldg(q3 + coff);
                vdst[kk*128] = v;
            }
        }
    };

    auto issueW = [&](int buf, int kc) {
        float* wb = wsb + buf*WSF;
        const float* wg = g_Wt + (size_t)kc*O_;
#pragma unroll
        for (int i = 0; i < 4; i++) {
            int idx = tid + i*256;
            int r = idx >> 5, q = idx & 31;
            cp16(wb + r*O_ + CSWZ(q)*4, wg + r*O_ + q*4);
        }
        asm volatile("cp.async.commit_group;");
    };

    const int to = tid & 15;
    const int tp = tid >> 4;
    const int wo0 = CSWZ(to*2)     * 4;
    const int wo1 = CSWZ(to*2 + 1) * 4;
    const int vo0 = CSWZ(tp*2)     * 4;
    const int vo1 = CSWZ(tp*2 + 1) * 4;

    unsigned long long acc2[8][4];
#pragma unroll
    for (int i = 0; i < 8; i++)
#pragma unroll
        for (int j = 0; j < 4; j++) acc2[i][j] = 0ull;

    // prologue
    issueW(0, 0);
    do_gather(0, vsb);

    int vcur = 0, vnxt = 1;
    const int NCH = CK_/KCM;   // 18
    for (int c = 0; c < NCH; c++) {
        if (c + 1 < NCH)
            do_gather((c+1)*KCM, vsb + vnxt*VSF);
        asm volatile("cp.async.wait_group 0;");
        __syncthreads();
        if (c + 1 < NCH)
            issueW((c+1) & 1, (c+1)*KCM);

        const float* wbuf = wsb + (c & 1)*WSF;
        const float* vbuf = vsb + vcur*VSF;

#pragma unroll 4
        for (int kk = 0; kk < KCM; kk++) {
            const float* wr = wbuf + kk*128;
            float4 a0 = *(const float4*)(wr + wo0);
            float4 a1 = *(const float4*)(wr + wo1);
            const float* vr = vbuf + kk*128;
            float4 v0 = *(const float4*)(vr + vo0);
            float4 v1 = *(const float4*)(vr + vo1);
            unsigned long long bv0 = ((const unsigned long long*)&v0)[0];
            unsigned long long bv1 = ((const unsigned long long*)&v0)[1];
            unsigned long long bv2 = ((const unsigned long long*)&v1)[0];
            unsigned long long bv3 = ((const unsigned long long*)&v1)[1];
            float av[8] = {a0.x, a0.y, a0.z, a0.w, a1.x, a1.y, a1.z, a1.w};
#pragma unroll
            for (int i = 0; i < 8; i++) {
                unsigned long long ai = pack2(av[i]);
                asm("fma.rn.f32x2 %0, %1, %2, %0;" : "+l"(acc2[i][0]) : "l"(ai), "l"(bv0));
                asm("fma.rn.f32x2 %0, %1, %2, %0;" : "+l"(acc2[i][1]) : "l"(ai), "l"(bv1));
                asm("fma.rn.f32x2 %0, %1, %2, %0;" : "+l"(acc2[i][2]) : "l"(ai), "l"(bv2));
                asm("fma.rn.f32x2 %0, %1, %2, %0;" : "+l"(acc2[i][3]) : "l"(ai), "l"(bv3));
            }
        }

        vcur = vnxt;
        vnxt = vnxt + 1; if (vnxt == 3) vnxt = 0;
    }

    const int o0 = to * 8;
    const int p0 = tp * 8;
#pragma unroll
    for (int i = 0; i < 8; i++) {
        float* dst = out + (size_t)(b*O_ + o0 + i)*HW_ + px0 + p0;
        *(float4*)(dst)     = *(float4*)(&acc2[i][0]);
        *(float4*)(dst + 4) = *(float4*)(&acc2[i][2]);
    }
}

// ---------------------------------------------------------------------------
extern "C" void kernel_launch(void* const* d_in, const int* in_sizes, int n_in,
                              void* d_out, int out_size)
{
    const float* x  = (const float*)d_in[0];
    const float* ow = (const float*)d_in[1];
    const float* ob = (const float*)d_in[2];
    const float* mw = (const float*)d_in[3];
    const float* mb = (const float*)d_in[4];
    const float* dw = (const float*)d_in[5];
    float* out = (float*)d_out;

    // params 27648 B + W 32768 B + V 49152 B = 109568 B -> 2 blocks/SM
    const int smemF = 4*NPAR*4 + 2*NPAR*4 + (2*WSF + 3*VSF)*4;
    cudaFuncSetAttribute(fused_kernel,
                         cudaFuncAttributeMaxDynamicSharedMemorySize, smemF);

    dim3 gA(3, 3, B_*CG_*2), bA(8, 32);   // 288 blocks
    conv_offmod_partial<<<gA, bA>>>(x, ow, mw);

    transpose_w<<<(O_*CK_ + 255)/256, 256>>>(dw);

    dim3 gF(HW_/128, B_);   // 72 x 4 = 288 blocks
    fused_kernel<<<gF, 256, smemF>>>(x, ob, mb, out);
}

// round 16
// speedup vs baseline: 1.6200x; 1.6200x over previous
#include <cuda_runtime.h>
#include <cstdint>

#define B_  4
#define C_  64
#define H_  96
#define W_  96
#define O_  128
#define HW_ (H_*W_)
#define K2_ 9
#define NJ_ 27
#define CK_ (C_*K2_)   // 576
#define CG_ 4
#define CPG (C_/CG_)   // 16

// scratch
__device__ float g_part[(size_t)CG_*B_*NJ_*HW_];
__device__ float g_Wt[(size_t)CK_*O_];   // transposed weights, k2-major

__device__ __forceinline__ void cp4z(float* s, const float* g, unsigned ssz) {
    unsigned sa = (unsigned)__cvta_generic_to_shared(s);
    asm volatile("cp.async.ca.shared.global [%0], [%1], 4, %2;"
                 :: "r"(sa), "l"(g), "r"(ssz));
}
__device__ __forceinline__ void cp16(float* s, const float* g) {
    unsigned sa = (unsigned)__cvta_generic_to_shared(s);
    asm volatile("cp.async.cg.shared.global [%0], [%1], 16;"
                 :: "r"(sa), "l"(g));
}
__device__ __forceinline__ unsigned long long pack2(float v) {
    unsigned long long r;
    unsigned int u = __float_as_uint(v);
    asm("mov.b64 %0, {%1, %1};" : "=l"(r) : "r"(u));
    return r;
}

// ---------------------------------------------------------------------------
// Kernel A: offset+modulator 3x3 conv (unchanged from R13/R14)
// ---------------------------------------------------------------------------
__global__ void __launch_bounds__(256) conv_offmod_partial(
    const float* __restrict__ x, const float* __restrict__ ow,
    const float* __restrict__ mw)
{
    __shared__ float ws[CPG*14*9];
    __shared__ float xs[2][34*36];

    const int tx = threadIdx.x;
    const int ty = threadIdx.y;
    const int tid = ty*8 + tx;
    const int zz = blockIdx.z;
    const int half = zz & 1;
    const int g = (zz >> 1) & 3;
    const int b = zz >> 3;
    const int JB = half * 14;
    const int jn = half ? 13 : 14;
    const int c0 = g * CPG;
    const int x0t = blockIdx.x*32 - 1;
    const int y0t = blockIdx.y*32 - 1;

    const int jn9 = jn * 9;
    for (int idx = tid; idx < CPG*jn9; idx += 256) {
        int c = idx / jn9, r = idx % jn9;
        int j = r / 9 + JB, t = r % 9;
        float v = (j < 18) ? ow[(j*64 + c0 + c)*9 + t]
                           : mw[((j-18)*64 + c0 + c)*9 + t];
        ws[idx] = v;
    }

    float acc[14][4];
#pragma unroll
    for (int j = 0; j < 14; j++)
#pragma unroll
        for (int i = 0; i < 4; i++) acc[j][i] = 0.f;

    const float* xb = x + (b*C_ + c0)*HW_;

    auto issueX = [&](int buf, int c) {
        const float* xc = xb + c*HW_;
#pragma unroll
        for (int it = 0; it < 5; it++) {
            int idx = tid + it*256;
            if (idx < 34*34) {
                int r = idx / 34, cc = idx % 34;
                int gy = y0t + r, gx = x0t + cc;
                bool ok = (gy >= 0 && gy < H_ && gx >= 0 && gx < W_);
                const float* gp = xc + (ok ? gy*W_ + gx : 0);
                cp4z(&xs[buf][r*36 + cc], gp, ok ? 4u : 0u);
            }
        }
        asm volatile("cp.async.commit_group;");
    };

    issueX(0, 0);

    for (int c = 0; c < CPG; c++) {
        if (c + 1 < CPG) {
            issueX((c+1) & 1, c+1);
            asm volatile("cp.async.wait_group 1;");
        } else {
            asm volatile("cp.async.wait_group 0;");
        }
        __syncthreads();

        const float* xt = xs[c & 1];
        float xv[3][6];
#pragma unroll
        for (int dy = 0; dy < 3; dy++)
#pragma unroll
            for (int dx = 0; dx < 6; dx++)
                xv[dy][dx] = xt[(ty + dy)*36 + tx*4 + dx];

        const float* wc = ws + c*jn9;
#pragma unroll
        for (int j = 0; j < 14; j++) {
            if (j < jn) {
#pragma unroll
                for (int t = 0; t < 9; t++) {
                    float wv = wc[j*9 + t];
#pragma unroll
                    for (int i = 0; i < 4; i++)
                        acc[j][i] = fmaf(wv, xv[t/3][t%3 + i], acc[j][i]);
                }
            }
        }
        __syncthreads();
    }

    const int h  = y0t + 1 + ty;
    const int w0 = x0t + 1 + tx*4;
    float* outb = g_part + ((size_t)(g*B_ + b)*NJ_ + JB)*HW_ + h*W_ + w0;
#pragma unroll
    for (int j = 0; j < 14; j++) {
        if (j < jn) {
            float4 v = make_float4(acc[j][0], acc[j][1], acc[j][2], acc[j][3]);
            *(float4*)(outb + (size_t)j*HW_) = v;
        }
    }
}

// ---------------------------------------------------------------------------
// Kernel T: transpose weights, k2-major: g_Wt[(k2*64+c)*O + o] = dw[o][c*9+k2]
// ---------------------------------------------------------------------------
__global__ void transpose_w(const float* __restrict__ dw)
{
    int i = blockIdx.x*256 + threadIdx.x;
    if (i < O_*CK_) {
        int o = i / CK_, r = i % CK_;
        int c = r / 9, k2 = r % 9;
        g_Wt[(size_t)(k2*C_ + c)*O_ + o] = dw[i];
    }
}

// ---------------------------------------------------------------------------
// Kernel F: FUSED gather + GEMM, k2-major K ordering (R14 schedule:
// double-buffered V and W, wait_group 1, two syncs per chunk).
// Params packed: wgt float4 + gof ushort4.
// ---------------------------------------------------------------------------
#define KCM 32
#define NPAR (K2_*128)
#define WSF (KCM*128)
#define VSF (KCM*128)
#define CSWZ(cx) ((cx) ^ (((cx) >> 3) & 1))

__global__ void __launch_bounds__(256, 2) fused_kernel(
    const float* __restrict__ x, const float* __restrict__ ob,
    const float* __restrict__ mb, float* __restrict__ out)
{
    extern __shared__ float sm[];
    float4*  wgt4 = (float4*)sm;                    // [1152] float4 (18432 B)
    ushort4* gof2 = (ushort4*)(sm + 4*NPAR);        // [1152] ushort4 (9216 B)
    float*   wsb  = sm + 4*NPAR + 2*NPAR;           // 2 x 4096 floats
    float*   vsb  = wsb + 2*WSF;                    // 2 x 4096 floats

    const int tid = threadIdx.x;
    const int b   = blockIdx.y;
    const int px0 = blockIdx.x * 128;

    const float* xb = x + b*C_*HW_;

    // ---- stage 0: bilinear params ----
    for (int t = tid; t < NPAR; t += 256) {
        int k2 = t >> 7, p = t & 127;
        int pg = px0 + p;
        int h  = pg / W_, w = pg % W_;

        float dy = ob[2*k2], dx = ob[2*k2+1], mv = mb[k2];
#pragma unroll
        for (int g = 0; g < CG_; g++) {
            const float* pb = g_part + (((size_t)g*B_ + b)*NJ_)*HW_ + pg;
            dy += pb[(size_t)(2*k2)*HW_];
            dx += pb[(size_t)(2*k2+1)*HW_];
            mv += pb[(size_t)(18+k2)*HW_];
        }
        float m = 2.f / (1.f + __expf(-mv));

        float py = (float)(h - 1 + k2/3) + dy;
        float px = (float)(w - 1 + k2%3) + dx;
        float fy = floorf(py), fx = floorf(px);
        float ly = py - fy,    lx = px - fx;
        int y0 = (int)fy, x0i = (int)fx;
        float vy0 = (y0   >= 0 && y0   < H_) ? 1.f : 0.f;
        float vy1 = (y0+1 >= 0 && y0+1 < H_) ? 1.f : 0.f;
        float vx0 = (x0i   >= 0 && x0i   < W_) ? 1.f : 0.f;
        float vx1 = (x0i+1 >= 0 && x0i+1 < W_) ? 1.f : 0.f;
        int cy0 = min(max(y0, 0), H_-1),   cy1 = min(max(y0+1, 0), H_-1);
        int cx0 = min(max(x0i, 0), W_-1),  cx1 = min(max(x0i+1, 0), W_-1);
        wgt4[t] = make_float4((1.f-ly)*(1.f-lx)*vy0*vx0*m,
                              (1.f-ly)*lx      *vy0*vx1*m,
                              ly*(1.f-lx)      *vy1*vx0*m,
                              ly*lx            *vy1*vx1*m);
        gof2[t] = make_ushort4((unsigned short)(cy0*W_),
                               (unsigned short)(cy1*W_),
                               (unsigned short)cx0,
                               (unsigned short)cx1);
    }
    __syncthreads();

    const int lane = tid & 31;
    const int wrow = tid >> 5;   // 0..7

    auto do_gather = [&](int kc, float* vbuf) {
        const int k2    = kc >> 6;
        const int cbase = kc & 63;
        const float* xcb = xb + (size_t)cbase*HW_;
#pragma unroll
        for (int rep = 0; rep < 4; rep++) {
            int p = lane + rep*32;
            int t = k2*128 + p;
            float4  wv = wgt4[t];
            ushort4 gg = gof2[t];
            const float* r0 = xcb + gg.x;
            const float* r1 = xcb + gg.y;
            const float* q0 = r0 + gg.z;
            const float* q1 = r0 + gg.w;
            const float* q2 = r1 + gg.z;
            const float* q3 = r1 + gg.w;
            int chunk = p >> 2;
            float* vdst = vbuf + (CSWZ(chunk) << 2) + (p & 3);
#pragma unroll
            for (int it = 0; it < 4; it++) {
                int kk = wrow + it*8;
                size_t coff = (size_t)kk*HW_;
                float v = wv.x*__ldg(q0 + coff) + wv.y*__ldg(q1 + coff)
                        + wv.z*__ldg(q2 + coff) + wv.w*__ldg(q3 + coff);
                vdst[kk*128] = v;
            }
        }
    };

    auto issueW = [&](int buf, int kc) {
        float* wb = wsb + buf*WSF;
        const float* wg = g_Wt + (size_t)kc*O_;
#pragma unroll
        for (int i = 0; i < 4; i++) {
            int idx = tid + i*256;
            int r = idx >> 5, q = idx & 31;
            cp16(wb + r*O_ + CSWZ(q)*4, wg + r*O_ + q*4);
        }
        asm volatile("cp.async.commit_group;");
    };

    const int to = tid & 15;
    const int tp = tid >> 4;
    const int wo0 = CSWZ(to*2)     * 4;
    const int wo1 = CSWZ(to*2 + 1) * 4;
    const int vo0 = CSWZ(tp*2)     * 4;
    const int vo1 = CSWZ(tp*2 + 1) * 4;

    unsigned long long acc2[8][4];
#pragma unroll
    for (int i = 0; i < 8; i++)
#pragma unroll
        for (int j = 0; j < 4; j++) acc2[i][j] = 0ull;

    issueW(0, 0);
    do_gather(0, vsb);

    const int NCH = CK_/KCM;   // 18
    for (int c = 0; c < NCH; c++) {
        int cur = c & 1;
        if (c + 1 < NCH) {
            issueW(cur ^ 1, (c+1)*KCM);
            do_gather((c+1)*KCM, vsb + (cur ^ 1)*VSF);
            asm volatile("cp.async.wait_group 1;");
        } else {
            asm volatile("cp.async.wait_group 0;");
        }
        __syncthreads();

        const float* wbuf = wsb + cur*WSF;
        const float* vbuf = vsb + cur*VSF;

#pragma unroll 4
        for (int kk = 0; kk < KCM; kk++) {
            const float* wr = wbuf + kk*128;
            float4 a0 = *(const float4*)(wr + wo0);
            float4 a1 = *(const float4*)(wr + wo1);
            const float* vr = vbuf + kk*128;
            float4 v0 = *(const float4*)(vr + vo0);
            float4 v1 = *(const float4*)(vr + vo1);
            unsigned long long bv0 = ((const unsigned long long*)&v0)[0];
            unsigned long long bv1 = ((const unsigned long long*)&v0)[1];
            unsigned long long bv2 = ((const unsigned long long*)&v1)[0];
            unsigned long long bv3 = ((const unsigned long long*)&v1)[1];
            float av[8] = {a0.x, a0.y, a0.z, a0.w, a1.x, a1.y, a1.z, a1.w};
#pragma unroll
            for (int i = 0; i < 8; i++) {
                unsigned long long ai = pack2(av[i]);
                asm("fma.rn.f32x2 %0, %1, %2, %0;" : "+l"(acc2[i][0]) : "l"(ai), "l"(bv0));
                asm("fma.rn.f32x2 %0, %1, %2, %0;" : "+l"(acc2[i][1]) : "l"(ai), "l"(bv1));
                asm("fma.rn.f32x2 %0, %1, %2, %0;" : "+l"(acc2[i][2]) : "l"(ai), "l"(bv2));
                asm("fma.rn.f32x2 %0, %1, %2, %0;" : "+l"(acc2[i][3]) : "l"(ai), "l"(bv3));
            }
        }
        __syncthreads();
    }

    const int o0 = to * 8;
    const int p0 = tp * 8;
#pragma unroll
    for (int i = 0; i < 8; i++) {
        float* dst = out + (size_t)(b*O_ + o0 + i)*HW_ + px0 + p0;
        *(float4*)(dst)     = *(float4*)(&acc2[i][0]);
        *(float4*)(dst + 4) = *(float4*)(&acc2[i][2]);
    }
}

// ---------------------------------------------------------------------------
extern "C" void kernel_launch(void* const* d_in, const int* in_sizes, int n_in,
                              void* d_out, int out_size)
{
    const float* x  = (const float*)d_in[0];
    const float* ow = (const float*)d_in[1];
    const float* ob = (const float*)d_in[2];
    const float* mw = (const float*)d_in[3];
    const float* mb = (const float*)d_in[4];
    const float* dw = (const float*)d_in[5];
    float* out = (float*)d_out;

    // params 27648 B + W 32768 B + V 32768 B = 93184 B -> 2 blocks/SM
    const int smemF = 4*NPAR*4 + 2*NPAR*4 + (2*WSF + 2*VSF)*4;
    cudaFuncSetAttribute(fused_kernel,
                         cudaFuncAttributeMaxDynamicSharedMemorySize, smemF);

    dim3 gA(3, 3, B_*CG_*2), bA(8, 32);   // 288 blocks
    conv_offmod_partial<<<gA, bA>>>(x, ow, mw);

    transpose_w<<<(O_*CK_ + 255)/256, 256>>>(dw);

    dim3 gF(HW_/128, B_);   // 72 x 4 = 288 blocks
    fused_kernel<<<gF, 256, smemF>>>(x, ob, mb, out);
}